// round 7
// baseline (speedup 1.0000x reference)
#include <cuda_runtime.h>
#include <math.h>

#define DDIM 128
#define KCODES 256
#define BM 64
#define DC 32
#define MAXB 8192   // max N/BM we support for partial buffer (N=524288 -> 8192)

typedef unsigned long long ull;

// Scratch (device globals: no allocation allowed)
__device__ __align__(16) float g_en[KCODES * DDIM];      // normalized codebook
__device__ float g_part[MAXB * KCODES];                  // per-CTA prob partial sums
__device__ float g_part2[32 * KCODES];                   // stage-2 partials

// packed f32x2 fma: d = a*b + d  (elementwise, exact fp32 per lane)
__device__ __forceinline__ void ffma2(ull& d, ull a, ull b) {
    asm("fma.rn.f32x2 %0, %1, %2, %0;" : "+l"(d) : "l"(a), "l"(b));
}
// duplicate a float into both halves of a b64 (alu pipe, not fma pipe)
__device__ __forceinline__ ull pack2(float x) {
    ull r; unsigned u = __float_as_uint(x);
    asm("mov.b64 %0, {%1, %1};" : "=l"(r) : "r"(u));
    return r;
}
__device__ __forceinline__ void unpack2(float& lo, float& hi, ull v) {
    unsigned a, b;
    asm("mov.b64 {%0, %1}, %2;" : "=r"(a), "=r"(b) : "l"(v));
    lo = __uint_as_float(a); hi = __uint_as_float(b);
}

// ---------------------------------------------------------------------------
// prep: e_n = e / max(||e||, 1e-12)
// ---------------------------------------------------------------------------
__global__ void prep_kernel(const float* __restrict__ emb) {
    int k = threadIdx.x;  // 256 threads, one code each
    const float* row = emb + k * DDIM;
    float ss = 0.f;
    #pragma unroll 8
    for (int d = 0; d < DDIM; d++) { float x = row[d]; ss = fmaf(x, x, ss); }
    float inv = 1.0f / fmaxf(sqrtf(ss), 1e-12f);
    #pragma unroll 8
    for (int d = 0; d < DDIM; d++) g_en[k * DDIM + d] = row[d] * inv;
}

// ---------------------------------------------------------------------------
// main: per 64-row tile — fp32 logits vs all 256 codes via packed f32x2 FMA,
//       argmax, softmax, z_q gather, per-CTA avg_prob partials.
// Thread map: tid = ty*16+tx ; rows = ty*4..ty*4+3 ;
//             codes = pairs (2tx+32i, 2tx+32i+1), i=0..7
// ---------------------------------------------------------------------------
__global__ void __launch_bounds__(256, 2) main_kernel(
    const float* __restrict__ z, const float* __restrict__ emb,
    const float* __restrict__ scale_p, float* __restrict__ out, int N)
{
    __shared__ __align__(16) float smem[2048 + 8192];   // 40 KB
    float* sZ = smem;                     // [DC][BM]      (d-major)
    float* sE = smem + 2048;              // [DC][KCODES]  (d-major)
    float* sRed = smem + 2048;            // alias of sE: [16][KCODES]

    const int tid = threadIdx.x;
    const int tx = tid & 15;
    const int ty = tid >> 4;
    const int m0 = blockIdx.x * BM;

    ull accp[4][8];                       // [row j][code pair i] packed f32x2
    #pragma unroll
    for (int j = 0; j < 4; j++)
        #pragma unroll
        for (int i = 0; i < 8; i++) accp[j][i] = 0ull;
    ull znp[4] = {0ull, 0ull, 0ull, 0ull};

    for (int dc = 0; dc < DDIM; dc += DC) {
        // load z tile chunk: 64 rows x 32 d (transposed into sZ[d][m]), coalesced
        #pragma unroll
        for (int it = 0; it < 2; it++) {
            int idx = tid + it * 256;        // 0..511
            int m = idx >> 3;
            int q = idx & 7;
            float4 v = *(const float4*)(z + (size_t)(m0 + m) * DDIM + dc + q * 4);
            sZ[(q * 4 + 0) * BM + m] = v.x;
            sZ[(q * 4 + 1) * BM + m] = v.y;
            sZ[(q * 4 + 2) * BM + m] = v.z;
            sZ[(q * 4 + 3) * BM + m] = v.w;
        }
        // load e_n chunk: 256 codes x 32 d (transposed into sE[d][k])
        #pragma unroll
        for (int it = 0; it < 8; it++) {
            int idx = tid + it * 256;        // 0..2047
            int kk = idx >> 3;
            int q = idx & 7;
            float4 v = *(const float4*)(g_en + kk * DDIM + dc + q * 4);
            sE[(q * 4 + 0) * KCODES + kk] = v.x;
            sE[(q * 4 + 1) * KCODES + kk] = v.y;
            sE[(q * 4 + 2) * KCODES + kk] = v.z;
            sE[(q * 4 + 3) * KCODES + kk] = v.w;
        }
        __syncthreads();

        #pragma unroll
        for (int d = 0; d < DC; d++) {
            ull zz[4];
            #pragma unroll
            for (int j = 0; j < 4; j++) zz[j] = pack2(sZ[d * BM + ty * 4 + j]);
            ull ek[8];
            const ull* ep = (const ull*)(sE + d * KCODES) + tx;  // pair tx+16i
            #pragma unroll
            for (int i = 0; i < 8; i++) ek[i] = ep[16 * i];      // LDS.64, imm offsets
            #pragma unroll
            for (int j = 0; j < 4; j++) {
                ffma2(znp[j], zz[j], zz[j]);
                #pragma unroll
                for (int i = 0; i < 8; i++) ffma2(accp[j][i], zz[j], ek[i]);
            }
        }
        __syncthreads();
    }

    // -------- epilogue --------
    const float s = *scale_p;
    const unsigned FULL = 0xFFFFFFFFu;
    float psum[16];
    #pragma unroll
    for (int i = 0; i < 16; i++) psum[i] = 0.f;

    #pragma unroll
    for (int j = 0; j < 4; j++) {
        const int m = m0 + ty * 4 + j;

        float a[16];
        #pragma unroll
        for (int i = 0; i < 8; i++) unpack2(a[2 * i], a[2 * i + 1], accp[j][i]);

        // local argmax; code(t) = 2tx + 32*(t>>1) + (t&1) is strictly increasing
        // in t, so strict > keeps the lowest index on ties (matches jnp.argmax)
        float bv = a[0];
        int   bi = 2 * tx;
        #pragma unroll
        for (int t = 1; t < 16; t++) {
            int c = 2 * tx + 32 * (t >> 1) + (t & 1);
            if (a[t] > bv) { bv = a[t]; bi = c; }
        }
        // shuffle-reduce over the 16-lane tx group (lane bits 0..3)
        #pragma unroll
        for (int o = 1; o < 16; o <<= 1) {
            float ov = __shfl_xor_sync(FULL, bv, o);
            int   oi = __shfl_xor_sync(FULL, bi, o);
            if (ov > bv || (ov == bv && oi < bi)) { bv = ov; bi = oi; }
        }

        float znlo, znhi;
        unpack2(znlo, znhi, znp[j]);          // both halves equal
        const float invn = 1.0f / fmaxf(sqrtf(znlo), 1e-12f);
        const float sc = s * invn;
        float p[16];
        float se = 0.f;
        #pragma unroll
        for (int t = 0; t < 16; t++) {
            p[t] = __expf(sc * (a[t] - bv));
            se += p[t];
        }
        #pragma unroll
        for (int o = 1; o < 16; o <<= 1) se += __shfl_xor_sync(FULL, se, o);
        const float rinv = 1.0f / se;
        #pragma unroll
        for (int t = 0; t < 16; t++) psum[t] = fmaf(p[t], rinv, psum[t]);

        // outputs: index (as float) + z_q gather (16 threads copy 128 floats)
        if (tx == 0) out[(size_t)N * DDIM + m] = (float)bi;
        const float4* src = (const float4*)(emb + (size_t)bi * DDIM);
        float4* dst = (float4*)(out + (size_t)m * DDIM);
        dst[tx]      = src[tx];
        dst[tx + 16] = src[tx + 16];
    }

    // per-CTA reduction of prob partials over ty, then write fixed slot
    #pragma unroll
    for (int i = 0; i < 8; i++) {
        float2 v = make_float2(psum[2 * i], psum[2 * i + 1]);
        *(float2*)(sRed + ty * KCODES + 2 * tx + 32 * i) = v;
    }
    __syncthreads();
    float tot = 0.f;
    #pragma unroll
    for (int r = 0; r < 16; r++) tot += sRed[r * KCODES + tid];
    g_part[(size_t)blockIdx.x * KCODES + tid] = tot;
}

// ---------------------------------------------------------------------------
// reduce1: 32 blocks x 256 threads; block r sums 256 CTA-partials per code.
// ---------------------------------------------------------------------------
__global__ void reduce1_kernel(int nb) {
    int r = blockIdx.x;
    int k = threadIdx.x;
    float sum = 0.f;
    for (int j = 0; j < 256; j++) {
        int b = r * 256 + j;
        if (b < nb) sum += g_part[(size_t)b * KCODES + k];
    }
    g_part2[r * KCODES + k] = sum;
}

// ---------------------------------------------------------------------------
// ppl: final perplexity = exp(-sum(avg_probs * log(avg_probs + 1e-10)))
// ---------------------------------------------------------------------------
__global__ void ppl_kernel(float* __restrict__ out, float invN, size_t off) {
    int k = threadIdx.x;  // 256 threads
    float a = 0.f;
    #pragma unroll
    for (int r = 0; r < 32; r++) a += g_part2[r * KCODES + k];
    a *= invN;
    float t = -a * logf(a + 1e-10f);

    __shared__ float red[8];
    #pragma unroll
    for (int o = 16; o; o >>= 1) t += __shfl_xor_sync(0xFFFFFFFFu, t, o);
    if ((k & 31) == 0) red[k >> 5] = t;
    __syncthreads();
    if (k < 8) {
        float v = red[k];
        #pragma unroll
        for (int o = 4; o; o >>= 1) v += __shfl_xor_sync(0xFFu, v, o);
        if (k == 0) out[off] = expf(v);
    }
}

// ---------------------------------------------------------------------------
extern "C" void kernel_launch(void* const* d_in, const int* in_sizes, int n_in,
                              void* d_out, int out_size) {
    const float* z     = (const float*)d_in[0];
    const float* emb   = (const float*)d_in[1];
    const float* scale = (const float*)d_in[2];
    float* out = (float*)d_out;

    const int N = in_sizes[0] / DDIM;
    const int nb = N / BM;

    prep_kernel<<<1, 256>>>(emb);
    main_kernel<<<nb, 256>>>(z, emb, scale, out, N);
    reduce1_kernel<<<32, 256>>>(nb);
    ppl_kernel<<<1, 256>>>(out, 1.0f / (float)N, (size_t)N * DDIM + (size_t)N);
}

// round 8
// speedup vs baseline: 1.0008x; 1.0008x over previous
#include <cuda_runtime.h>
#include <math.h>

#define DDIM 128
#define KCODES 256
#define BM 64
#define DC 32
#define MAXB 8192   // max N/BM we support for partial buffer (N=524288 -> 8192)

typedef unsigned long long ull;

// Scratch (device globals: no allocation allowed)
__device__ __align__(16) float g_en[KCODES * DDIM];      // normalized codebook
__device__ float g_part[MAXB * KCODES];                  // per-CTA prob partial sums
__device__ float g_part2[32 * KCODES];                   // stage-2 partials

// packed f32x2 fma: d = a*b + d  (elementwise, exact fp32 per lane)
__device__ __forceinline__ void ffma2(ull& d, ull a, ull b) {
    asm("fma.rn.f32x2 %0, %1, %2, %0;" : "+l"(d) : "l"(a), "l"(b));
}
// duplicate a float into both halves of a b64 (alu pipe, not fma pipe)
__device__ __forceinline__ ull pack2(float x) {
    ull r; unsigned u = __float_as_uint(x);
    asm("mov.b64 %0, {%1, %1};" : "=l"(r) : "r"(u));
    return r;
}
__device__ __forceinline__ void unpack2(float& lo, float& hi, ull v) {
    unsigned a, b;
    asm("mov.b64 {%0, %1}, %2;" : "=r"(a), "=r"(b) : "l"(v));
    lo = __uint_as_float(a); hi = __uint_as_float(b);
}

// ---------------------------------------------------------------------------
// prep: e_n = e / max(||e||, 1e-12)
// ---------------------------------------------------------------------------
__global__ void prep_kernel(const float* __restrict__ emb) {
    int k = threadIdx.x;  // 256 threads, one code each
    const float* row = emb + k * DDIM;
    float ss = 0.f;
    #pragma unroll 8
    for (int d = 0; d < DDIM; d++) { float x = row[d]; ss = fmaf(x, x, ss); }
    float inv = 1.0f / fmaxf(sqrtf(ss), 1e-12f);
    #pragma unroll 8
    for (int d = 0; d < DDIM; d++) g_en[k * DDIM + d] = row[d] * inv;
}

// ---------------------------------------------------------------------------
// main: per 64-row tile — fp32 logits vs all 256 codes via packed f32x2 FMA,
//       argmax, softmax, z_q gather, per-CTA avg_prob partials.
// Thread map: tid = ty*16+tx ; rows = ty*4..ty*4+3 ;
//             codes = pairs (2tx+32i, 2tx+32i+1), i=0..7
// ---------------------------------------------------------------------------
__global__ void __launch_bounds__(256, 2) main_kernel(
    const float* __restrict__ z, const float* __restrict__ emb,
    const float* __restrict__ scale_p, float* __restrict__ out, int N)
{
    __shared__ __align__(16) float smem[2048 + 8192];   // 40 KB
    float* sZ = smem;                     // [DC][BM]      (d-major)
    float* sE = smem + 2048;              // [DC][KCODES]  (d-major)
    float* sRed = smem + 2048;            // alias of sE: [16][KCODES]

    const int tid = threadIdx.x;
    const int tx = tid & 15;
    const int ty = tid >> 4;
    const int m0 = blockIdx.x * BM;

    ull accp[4][8];                       // [row j][code pair i] packed f32x2
    #pragma unroll
    for (int j = 0; j < 4; j++)
        #pragma unroll
        for (int i = 0; i < 8; i++) accp[j][i] = 0ull;
    ull znp[4] = {0ull, 0ull, 0ull, 0ull};

    for (int dc = 0; dc < DDIM; dc += DC) {
        // load z tile chunk: 64 rows x 32 d (transposed into sZ[d][m]), coalesced
        #pragma unroll
        for (int it = 0; it < 2; it++) {
            int idx = tid + it * 256;        // 0..511
            int m = idx >> 3;
            int q = idx & 7;
            float4 v = *(const float4*)(z + (size_t)(m0 + m) * DDIM + dc + q * 4);
            sZ[(q * 4 + 0) * BM + m] = v.x;
            sZ[(q * 4 + 1) * BM + m] = v.y;
            sZ[(q * 4 + 2) * BM + m] = v.z;
            sZ[(q * 4 + 3) * BM + m] = v.w;
        }
        // load e_n chunk: 256 codes x 32 d (transposed into sE[d][k])
        #pragma unroll
        for (int it = 0; it < 8; it++) {
            int idx = tid + it * 256;        // 0..2047
            int kk = idx >> 3;
            int q = idx & 7;
            float4 v = *(const float4*)(g_en + kk * DDIM + dc + q * 4);
            sE[(q * 4 + 0) * KCODES + kk] = v.x;
            sE[(q * 4 + 1) * KCODES + kk] = v.y;
            sE[(q * 4 + 2) * KCODES + kk] = v.z;
            sE[(q * 4 + 3) * KCODES + kk] = v.w;
        }
        __syncthreads();

        #pragma unroll
        for (int d = 0; d < DC; d++) {
            ull zz[4];
            #pragma unroll
            for (int j = 0; j < 4; j++) zz[j] = pack2(sZ[d * BM + ty * 4 + j]);
            ull ek[8];
            const ull* ep = (const ull*)(sE + d * KCODES) + tx;  // pair tx+16i
            #pragma unroll
            for (int i = 0; i < 8; i++) ek[i] = ep[16 * i];      // LDS.64, imm offsets
            #pragma unroll
            for (int j = 0; j < 4; j++) {
                ffma2(znp[j], zz[j], zz[j]);
                #pragma unroll
                for (int i = 0; i < 8; i++) ffma2(accp[j][i], zz[j], ek[i]);
            }
        }
        __syncthreads();
    }

    // -------- epilogue --------
    const float s = *scale_p;
    const unsigned FULL = 0xFFFFFFFFu;
    float psum[16];
    #pragma unroll
    for (int i = 0; i < 16; i++) psum[i] = 0.f;

    #pragma unroll
    for (int j = 0; j < 4; j++) {
        const int m = m0 + ty * 4 + j;

        float a[16];
        #pragma unroll
        for (int i = 0; i < 8; i++) unpack2(a[2 * i], a[2 * i + 1], accp[j][i]);

        // local argmax; code(t) = 2tx + 32*(t>>1) + (t&1) is strictly increasing
        // in t, so strict > keeps the lowest index on ties (matches jnp.argmax)
        float bv = a[0];
        int   bi = 2 * tx;
        #pragma unroll
        for (int t = 1; t < 16; t++) {
            int c = 2 * tx + 32 * (t >> 1) + (t & 1);
            if (a[t] > bv) { bv = a[t]; bi = c; }
        }
        // shuffle-reduce over the 16-lane tx group (lane bits 0..3)
        #pragma unroll
        for (int o = 1; o < 16; o <<= 1) {
            float ov = __shfl_xor_sync(FULL, bv, o);
            int   oi = __shfl_xor_sync(FULL, bi, o);
            if (ov > bv || (ov == bv && oi < bi)) { bv = ov; bi = oi; }
        }

        float znlo, znhi;
        unpack2(znlo, znhi, znp[j]);          // both halves equal
        const float invn = 1.0f / fmaxf(sqrtf(znlo), 1e-12f);
        const float sc = s * invn;
        float p[16];
        float se = 0.f;
        #pragma unroll
        for (int t = 0; t < 16; t++) {
            p[t] = __expf(sc * (a[t] - bv));
            se += p[t];
        }
        #pragma unroll
        for (int o = 1; o < 16; o <<= 1) se += __shfl_xor_sync(FULL, se, o);
        const float rinv = 1.0f / se;
        #pragma unroll
        for (int t = 0; t < 16; t++) psum[t] = fmaf(p[t], rinv, psum[t]);

        // outputs: index (as float) + z_q gather (16 threads copy 128 floats)
        if (tx == 0) out[(size_t)N * DDIM + m] = (float)bi;
        const float4* src = (const float4*)(emb + (size_t)bi * DDIM);
        float4* dst = (float4*)(out + (size_t)m * DDIM);
        dst[tx]      = src[tx];
        dst[tx + 16] = src[tx + 16];
    }

    // per-CTA reduction of prob partials over ty, then write fixed slot
    #pragma unroll
    for (int i = 0; i < 8; i++) {
        float2 v = make_float2(psum[2 * i], psum[2 * i + 1]);
        *(float2*)(sRed + ty * KCODES + 2 * tx + 32 * i) = v;
    }
    __syncthreads();
    float tot = 0.f;
    #pragma unroll
    for (int r = 0; r < 16; r++) tot += sRed[r * KCODES + tid];
    g_part[(size_t)blockIdx.x * KCODES + tid] = tot;
}

// ---------------------------------------------------------------------------
// reduce1: 32 blocks x 256 threads; block r sums 256 CTA-partials per code.
// ---------------------------------------------------------------------------
__global__ void reduce1_kernel(int nb) {
    int r = blockIdx.x;
    int k = threadIdx.x;
    float sum = 0.f;
    for (int j = 0; j < 256; j++) {
        int b = r * 256 + j;
        if (b < nb) sum += g_part[(size_t)b * KCODES + k];
    }
    g_part2[r * KCODES + k] = sum;
}

// ---------------------------------------------------------------------------
// ppl: final perplexity = exp(-sum(avg_probs * log(avg_probs + 1e-10)))
// ---------------------------------------------------------------------------
__global__ void ppl_kernel(float* __restrict__ out, float invN, size_t off) {
    int k = threadIdx.x;  // 256 threads
    float a = 0.f;
    #pragma unroll
    for (int r = 0; r < 32; r++) a += g_part2[r * KCODES + k];
    a *= invN;
    float t = -a * logf(a + 1e-10f);

    __shared__ float red[8];
    #pragma unroll
    for (int o = 16; o; o >>= 1) t += __shfl_xor_sync(0xFFFFFFFFu, t, o);
    if ((k & 31) == 0) red[k >> 5] = t;
    __syncthreads();
    if (k < 8) {
        float v = red[k];
        #pragma unroll
        for (int o = 4; o; o >>= 1) v += __shfl_xor_sync(0xFFu, v, o);
        if (k == 0) out[off] = expf(v);
    }
}

// ---------------------------------------------------------------------------
extern "C" void kernel_launch(void* const* d_in, const int* in_sizes, int n_in,
                              void* d_out, int out_size) {
    const float* z     = (const float*)d_in[0];
    const float* emb   = (const float*)d_in[1];
    const float* scale = (const float*)d_in[2];
    float* out = (float*)d_out;

    const int N = in_sizes[0] / DDIM;
    const int nb = N / BM;

    prep_kernel<<<1, 256>>>(emb);
    main_kernel<<<nb, 256>>>(z, emb, scale, out, N);
    reduce1_kernel<<<32, 256>>>(nb);
    ppl_kernel<<<1, 256>>>(out, 1.0f / (float)N, (size_t)N * DDIM + (size_t)N);
}

// round 12
// speedup vs baseline: 1.0061x; 1.0053x over previous
#include <cuda_runtime.h>
#include <cuda_bf16.h>
#include <math.h>

#define DDIM 128
#define KCODES 256
#define BM 128
#define NB_MAX 8192
#define FIXCAP 131072

typedef unsigned int u32;

// ----------------- device scratch (no allocations allowed) -----------------
__device__ __align__(16) float g_en[KCODES * DDIM];              // normalized codebook fp32
__device__ __align__(16) unsigned char g_bimg[2][KCODES * 256];  // bf16 hi/lo images, swizzled
__device__ float g_part[NB_MAX * KCODES];
__device__ float g_part2[32 * KCODES];
__device__ int   g_cnt;
__device__ int   g_fix[FIXCAP];

// ----------------- helpers -----------------
// XOR swizzle: rows are 256B (128 bf16); 16B granule index XORed with row&7
// -> 8 consecutive rows hit 8 distinct bank groups (conflict-free ldmatrix).
__device__ __forceinline__ u32 sw_off(u32 row, u32 byte) {
    return row * 256u + ((((byte >> 4) ^ (row & 7u)) << 4) | (byte & 15u));
}
__device__ __forceinline__ u32 smem_u32(const void* p) {
    u32 a; asm("{ .reg .u64 t; cvta.to.shared.u64 t, %1; cvt.u32.u64 %0, t; }" : "=r"(a) : "l"(p));
    return a;
}
__device__ __forceinline__ void ldsm4(u32& r0, u32& r1, u32& r2, u32& r3, u32 a) {
    asm volatile("ldmatrix.sync.aligned.m8n8.x4.shared.b16 {%0,%1,%2,%3}, [%4];"
        : "=r"(r0), "=r"(r1), "=r"(r2), "=r"(r3) : "r"(a));
}
__device__ __forceinline__ void hmma(float* c, u32 a0, u32 a1, u32 a2, u32 a3, u32 b0, u32 b1) {
    asm volatile("mma.sync.aligned.m16n8k16.row.col.f32.bf16.bf16.f32 "
        "{%0,%1,%2,%3}, {%4,%5,%6,%7}, {%8,%9}, {%0,%1,%2,%3};"
        : "+f"(c[0]), "+f"(c[1]), "+f"(c[2]), "+f"(c[3])
        : "r"(a0), "r"(a1), "r"(a2), "r"(a3), "r"(b0), "r"(b1));
}
__device__ __forceinline__ u32 bpack(__nv_bfloat16 x, __nv_bfloat16 y) {
    __nv_bfloat162 h = __halves2bfloat162(x, y);
    return *(u32*)&h;
}

// smem layout (bytes from dynamic smem base)
#define SM_B    0         // 2 x 65536 (codebook hi/lo images)
#define SM_A    131072    // 2 x 32768 (z tile hi/lo images)
#define SM_SQ   196608    // 128 f : row sumsq
#define SM_SC   197120    // 128 f : per-row exp scale
#define SM_SUM  197632    // [2][128] f : per-side sum-exp
#define SM_B1   198656    // [2][128] f : per-side best exp
#define SM_B2   199680    // [2][128] f : per-side 2nd exp
#define SM_IDX  200704    // [2][128] i : per-side argmax
#define SM_INV  201728    // 128 f : 1/S
#define SM_IDXF 202240    // 128 i : final argmax
#define SM_PS   202752    // [16][128] f : per-warp col prob sums
#define SMEM_SZ 210944

// ---------------------------------------------------------------------------
// prep: e_n fp32 + swizzled bf16 hi/lo codebook images + reset fix counter
// ---------------------------------------------------------------------------
__global__ void prep_kernel(const float* __restrict__ emb) {
    int k = threadIdx.x;                 // one code per thread (256)
    if (k == 0) g_cnt = 0;
    const float* row = emb + k * DDIM;
    float ss = 0.f;
    #pragma unroll 8
    for (int d = 0; d < DDIM; d++) { float x = row[d]; ss = fmaf(x, x, ss); }
    float inv = 1.0f / fmaxf(sqrtf(ss), 1e-12f);
    for (int d = 0; d < DDIM; d++) {
        float en = row[d] * inv;
        g_en[k * DDIM + d] = en;
        __nv_bfloat16 hi = __float2bfloat16_rn(en);
        __nv_bfloat16 lo = __float2bfloat16_rn(en - __bfloat162float(hi));
        u32 off = sw_off((u32)k, (u32)(d * 2));
        *(__nv_bfloat16*)(g_bimg[0] + off) = hi;
        *(__nv_bfloat16*)(g_bimg[1] + off) = lo;
    }
}

// ---------------------------------------------------------------------------
// main: persistent CTAs, 512 thr. Per 128-row tile: 3-term bf16-split HMMA
// GEMM (registers) -> softmax/argmax/top2 epilogue + z_q gather + partials.
// warp w: rows (w&7)*16..+15, codes (w>>3)*128..+127.
// ---------------------------------------------------------------------------
__global__ void __launch_bounds__(512, 1)
main_kernel(const float* __restrict__ z, const float* __restrict__ emb,
            const float* __restrict__ scale_p, float* __restrict__ out,
            int N, int nb)
{
    extern __shared__ unsigned char sm[];
    const u32 smb = smem_u32(sm);
    float* sq   = (float*)(sm + SM_SQ);
    float* sSc  = (float*)(sm + SM_SC);
    float* sSum = (float*)(sm + SM_SUM);
    float* sB1  = (float*)(sm + SM_B1);
    float* sB2  = (float*)(sm + SM_B2);
    int*   sIdx = (int*)(sm + SM_IDX);
    float* sInv = (float*)(sm + SM_INV);
    int*   sIdxF= (int*)(sm + SM_IDXF);
    float* sPS  = (float*)(sm + SM_PS);

    const int tid  = threadIdx.x;
    const int wid  = tid >> 5, lane = tid & 31;
    const int side = wid >> 3, rb = wid & 7;
    const int g    = lane >> 2, t = lane & 3;
    const float scl = *scale_p;

    // copy codebook images to smem once (131072 B)
    {
        const float4* src = (const float4*)g_bimg;
        float4* dst = (float4*)sm;
        #pragma unroll
        for (int i = 0; i < 16; i++) dst[i * 512 + tid] = src[i * 512 + tid];
    }

    // per-lane ldmatrix address components
    const u32 aRow = (u32)(rb * 16 + (lane & 15));
    const u32 aKad = (u32)((lane >> 4) * 16);
    const u32 bRow = (u32)(side * 128 + (lane & 7) + (lane >> 4) * 8);
    const u32 bKad = (u32)(((lane >> 3) & 1) * 16);
    const u32 aBase = smb + SM_A;
    const u32 bBase = smb + SM_B;

    __syncthreads();

    for (int bid = blockIdx.x; bid < nb; bid += gridDim.x) {
        const int m0 = bid * BM;

        // ---- convert z tile -> hi/lo bf16 images + row sumsq (warp per row) ----
        #pragma unroll
        for (int it = 0; it < 8; it++) {
            int row = it * 16 + wid;
            float4 v = ((const float4*)(z + (size_t)(m0 + row) * DDIM))[lane];
            float ss = fmaf(v.x, v.x, fmaf(v.y, v.y, fmaf(v.z, v.z, v.w * v.w)));
            #pragma unroll
            for (int o = 16; o; o >>= 1) ss += __shfl_xor_sync(~0u, ss, o);
            if (lane == 0) sq[row] = ss;
            __nv_bfloat16 hx = __float2bfloat16_rn(v.x), hy = __float2bfloat16_rn(v.y);
            __nv_bfloat16 hz = __float2bfloat16_rn(v.z), hw = __float2bfloat16_rn(v.w);
            __nv_bfloat16 lx = __float2bfloat16_rn(v.x - __bfloat162float(hx));
            __nv_bfloat16 ly = __float2bfloat16_rn(v.y - __bfloat162float(hy));
            __nv_bfloat16 lz = __float2bfloat16_rn(v.z - __bfloat162float(hz));
            __nv_bfloat16 lw = __float2bfloat16_rn(v.w - __bfloat162float(hw));
            u32 off = sw_off((u32)row, (u32)(lane * 8));
            *(uint2*)(sm + SM_A + off)         = make_uint2(bpack(hx, hy), bpack(hz, hw));
            *(uint2*)(sm + SM_A + 32768 + off) = make_uint2(bpack(lx, ly), bpack(lz, lw));
        }
        __syncthreads();
        if (tid < 128) sSc[tid] = scl / fmaxf(sqrtf(sq[tid]), 1e-12f);

        // ---- GEMM: 3 split products (hh, lh, hl), 8 k-steps each ----
        float acc[16][4];
        #pragma unroll
        for (int n = 0; n < 16; n++) {
            acc[n][0] = 0.f; acc[n][1] = 0.f; acc[n][2] = 0.f; acc[n][3] = 0.f;
        }
        #pragma unroll
        for (int prod = 0; prod < 3; prod++) {
            const u32 aOff = (prod == 1) ? 32768u : 0u;
            const u32 bOff = (prod == 2) ? 65536u : 0u;
            #pragma unroll
            for (int ks = 0; ks < 8; ks++) {
                u32 a0, a1, a2, a3;
                ldsm4(a0, a1, a2, a3, aBase + aOff + sw_off(aRow, (u32)(ks * 32) + aKad));
                #pragma unroll
                for (int p = 0; p < 8; p++) {
                    u32 b0, b1, b2, b3;
                    ldsm4(b0, b1, b2, b3, bBase + bOff + sw_off(bRow + (u32)(p * 16), (u32)(ks * 32) + bKad));
                    hmma(acc[2 * p],     a0, a1, a2, a3, b0, b1);
                    hmma(acc[2 * p + 1], a0, a1, a2, a3, b2, b3);
                }
            }
        }
        __syncthreads();   // sSc visible everywhere

        // ---- pass 1: exps (overwrite acc), sum, top-2, argmax ----
        const int row0 = rb * 16 + g, row1 = row0 + 8;
        const float sc0 = sSc[row0], sc1 = sSc[row1];
        float s0 = 0.f, s1 = 0.f;
        float a1v = -1e30f, a2v = -1e30f, b1v = -1e30f, b2v = -1e30f;
        int ai = 0, bi = 0;
        const int colB = side * 128 + t * 2;
        #pragma unroll
        for (int n = 0; n < 16; n++) {
            #pragma unroll
            for (int b = 0; b < 2; b++) {
                int c = colB + 8 * n + b;
                float e0 = __expf(sc0 * acc[n][b]);     acc[n][b] = e0;     s0 += e0;
                if (e0 > a1v) { a2v = a1v; a1v = e0; ai = c; } else a2v = fmaxf(a2v, e0);
                float e1 = __expf(sc1 * acc[n][b + 2]); acc[n][b + 2] = e1; s1 += e1;
                if (e1 > b1v) { b2v = b1v; b1v = e1; bi = c; } else b2v = fmaxf(b2v, e1);
            }
        }
        #pragma unroll
        for (int o = 1; o < 4; o <<= 1) {
            s0 += __shfl_xor_sync(~0u, s0, o);
            s1 += __shfl_xor_sync(~0u, s1, o);
            float ov, o2; int oi;
            ov = __shfl_xor_sync(~0u, a1v, o); o2 = __shfl_xor_sync(~0u, a2v, o); oi = __shfl_xor_sync(~0u, ai, o);
            if (ov > a1v || (ov == a1v && oi < ai)) { a2v = fmaxf(a1v, o2); a1v = ov; ai = oi; }
            else a2v = fmaxf(a2v, ov);
            ov = __shfl_xor_sync(~0u, b1v, o); o2 = __shfl_xor_sync(~0u, b2v, o); oi = __shfl_xor_sync(~0u, bi, o);
            if (ov > b1v || (ov == b1v && oi < bi)) { b2v = fmaxf(b1v, o2); b1v = ov; bi = oi; }
            else b2v = fmaxf(b2v, ov);
        }
        if (t == 0) {
            sSum[side * 128 + row0] = s0; sB1[side * 128 + row0] = a1v;
            sB2[side * 128 + row0] = a2v; sIdx[side * 128 + row0] = ai;
            sSum[side * 128 + row1] = s1; sB1[side * 128 + row1] = b1v;
            sB2[side * 128 + row1] = b2v; sIdx[side * 128 + row1] = bi;
        }
        __syncthreads();

        // ---- combine sides, fixup guard, write index ----
        if (tid < 128) {
            int r = tid;
            float S = sSum[r] + sSum[128 + r];
            float x1 = sB1[r], x2 = sB2[r]; int xi = sIdx[r];
            float y1 = sB1[128 + r], y2 = sB2[128 + r]; int yi = sIdx[128 + r];
            float t1, t2; int ti;
            if (y1 > x1) { t1 = y1; ti = yi; t2 = fmaxf(x1, y2); }
            else         { t1 = x1; ti = xi; t2 = fmaxf(x2, y1); }   // tie -> lower side (lower idx)
            if (t2 >= t1 * 0.999f) {          // exp-ratio guard ~ dlogit < 1e-3
                int p = atomicAdd(&g_cnt, 1);
                if (p < FIXCAP) g_fix[p] = m0 + r;
            }
            sInv[r] = 1.0f / S;
            sIdxF[r] = ti;
            out[(size_t)N * DDIM + (m0 + r)] = (float)ti;
        }
        __syncthreads();

        // ---- pass 2: prob column sums (acc holds exps) ----
        {
            float ri0 = sInv[row0], ri1 = sInv[row1];
            #pragma unroll
            for (int n = 0; n < 16; n++) {
                float c0 = acc[n][0] * ri0 + acc[n][2] * ri1;
                float c1 = acc[n][1] * ri0 + acc[n][3] * ri1;
                #pragma unroll
                for (int o = 4; o < 32; o <<= 1) {
                    c0 += __shfl_xor_sync(~0u, c0, o);
                    c1 += __shfl_xor_sync(~0u, c1, o);
                }
                if (g == 0) {
                    sPS[wid * 128 + 8 * n + 2 * t]     = c0;
                    sPS[wid * 128 + 8 * n + 2 * t + 1] = c1;
                }
            }
        }
        // ---- z_q gather (warp per row, fully coalesced) ----
        #pragma unroll
        for (int it = 0; it < 8; it++) {
            int row = it * 16 + wid;
            int ci = sIdxF[row];
            const float4* src = (const float4*)(emb + (size_t)ci * DDIM);
            float4* dst = (float4*)(out + (size_t)(m0 + row) * DDIM);
            dst[lane] = src[lane];
        }
        __syncthreads();
        if (tid < 256) {
            int col = tid;
            int wb = (col >> 7) * 8, cc = col & 127;
            float s = 0.f;
            #pragma unroll
            for (int w8 = 0; w8 < 8; w8++) s += sPS[(wb + w8) * 128 + cc];
            g_part[(size_t)bid * KCODES + col] = s;
        }
        __syncthreads();
    }
}

// ---------------------------------------------------------------------------
// fixup: recompute near-tie rows with exact sequential fp32 dots.
// ---------------------------------------------------------------------------
__global__ void fix_kernel(const float* __restrict__ z, const float* __restrict__ emb,
                           float* __restrict__ out, int N)
{
    int cnt = g_cnt; if (cnt > FIXCAP) cnt = FIXCAP;
    const int lane = threadIdx.x & 31;
    const int gw = (blockIdx.x * blockDim.x + threadIdx.x) >> 5;
    const int nw = (gridDim.x * blockDim.x) >> 5;
    const unsigned FULL = 0xFFFFFFFFu;

    for (int w = gw; w < cnt; w += nw) {
        const int m = g_fix[w];
        const float* zr = z + (size_t)m * DDIM;
        float bv = -1e30f; int bi = 0;
        #pragma unroll 1
        for (int i = 0; i < 8; i++) {
            const int c = lane + 32 * i;
            const float* er = g_en + (size_t)c * DDIM;
            float acc = 0.f;
            #pragma unroll 8
            for (int d = 0; d < DDIM; d++) acc = fmaf(zr[d], er[d], acc);
            if (acc > bv) { bv = acc; bi = c; }
        }
        #pragma unroll
        for (int o = 1; o < 32; o <<= 1) {
            float ov = __shfl_xor_sync(FULL, bv, o);
            int   oi = __shfl_xor_sync(FULL, bi, o);
            if (ov > bv || (ov == bv && oi < bi)) { bv = ov; bi = oi; }
        }
        if (lane == 0) out[(size_t)N * DDIM + m] = (float)bi;
        const float4* src = (const float4*)(emb + (size_t)bi * DDIM);
        float4* dst = (float4*)(out + (size_t)m * DDIM);
        dst[lane] = src[lane];
    }
}

// ---------------------------------------------------------------------------
__global__ void reduce1_kernel(int nb) {
    int r = blockIdx.x, k = threadIdx.x;
    float sum = 0.f;
    for (int j = 0; j < 256; j++) {
        int b = r * 256 + j;
        if (b < nb) sum += g_part[(size_t)b * KCODES + k];
    }
    g_part2[r * KCODES + k] = sum;
}

__global__ void ppl_kernel(float* __restrict__ out, float invN, size_t off) {
    int k = threadIdx.x;
    float a = 0.f;
    #pragma unroll
    for (int r = 0; r < 32; r++) a += g_part2[r * KCODES + k];
    a *= invN;
    float t = -a * logf(a + 1e-10f);
    __shared__ float red[8];
    #pragma unroll
    for (int o = 16; o; o >>= 1) t += __shfl_xor_sync(0xFFFFFFFFu, t, o);
    if ((k & 31) == 0) red[k >> 5] = t;
    __syncthreads();
    if (k < 8) {
        float v = red[k];
        #pragma unroll
        for (int o = 4; o; o >>= 1) v += __shfl_xor_sync(0xFFu, v, o);
        if (k == 0) out[off] = expf(v);
    }
}

// ---------------------------------------------------------------------------
extern "C" void kernel_launch(void* const* d_in, const int* in_sizes, int n_in,
                              void* d_out, int out_size) {
    const float* z     = (const float*)d_in[0];
    const float* emb   = (const float*)d_in[1];
    const float* scale = (const float*)d_in[2];
    float* out = (float*)d_out;

    const int N  = in_sizes[0] / DDIM;
    const int nb = N / BM;

    static int attr_set = 0;
    if (!attr_set) {
        cudaFuncSetAttribute(main_kernel, cudaFuncAttributeMaxDynamicSharedMemorySize, SMEM_SZ);
        attr_set = 1;
    }

    prep_kernel<<<1, 256>>>(emb);
    main_kernel<<<148, 512, SMEM_SZ>>>(z, emb, scale, out, N, nb);
    fix_kernel<<<256, 256>>>(z, emb, out, N);
    reduce1_kernel<<<32, 256>>>(nb);
    ppl_kernel<<<1, 256>>>(out, 1.0f / (float)N, (size_t)N * DDIM + (size_t)N);
}